// round 1
// baseline (speedup 1.0000x reference)
#include <cuda_runtime.h>

#define BATCH 4
#define SLEN  4096
#define DDIM  1024
#define WIN   256
#define SPAD  (SLEN + 2 * WIN)        // 4608 padded rows per batch for K/V
#define NCOL  (128 + 2 * WIN)         // 640 score columns per query tile
#define QT_PER_B (SLEN / 128)         // 32 query tiles per batch
#define NEGV  (-1e10f)

// Scratch (device globals: allocation-free, zero-initialized once at load;
// pad rows of g_K/g_V are never written so they stay zero).
__device__ float g_Q[(size_t)BATCH * SLEN * DDIM];
__device__ float g_K[(size_t)BATCH * SPAD * DDIM];
__device__ float g_V[(size_t)BATCH * SPAD * DDIM];
__device__ float g_P[(size_t)BATCH * SLEN * NCOL];

// ---------------------------------------------------------------------------
// Projection GEMM: C[m,n] = sum_k A[m,k] * W[n,k]
// which: 0 -> g_Q (unpadded rows), 1 -> g_K (padded), 2 -> g_V (padded)
// ---------------------------------------------------------------------------
__global__ void __launch_bounds__(256, 2) proj_kernel(
    const float* __restrict__ A, const float* __restrict__ W, int which)
{
    __shared__ __align__(16) float As[8][132];
    __shared__ __align__(16) float Bs[8][132];

    const int tid = threadIdx.x;
    const int tx  = tid & 15;
    const int ty  = tid >> 4;
    const int m0  = blockIdx.y * 128;
    const int n0  = blockIdx.x * 128;
    const int lrow = tid >> 1;          // 0..127
    const int lcol = (tid & 1) * 4;     // 0 or 4

    const float* Ap = A + (size_t)(m0 + lrow) * DDIM + lcol;
    const float* Wp = W + (size_t)(n0 + lrow) * DDIM + lcol;

    float acc[8][8];
#pragma unroll
    for (int i = 0; i < 8; i++)
#pragma unroll
        for (int j = 0; j < 8; j++) acc[i][j] = 0.f;

    for (int k0 = 0; k0 < DDIM; k0 += 8) {
        float4 av = *(const float4*)(Ap + k0);
        float4 wv = *(const float4*)(Wp + k0);
        As[lcol + 0][lrow] = av.x; As[lcol + 1][lrow] = av.y;
        As[lcol + 2][lrow] = av.z; As[lcol + 3][lrow] = av.w;
        Bs[lcol + 0][lrow] = wv.x; Bs[lcol + 1][lrow] = wv.y;
        Bs[lcol + 2][lrow] = wv.z; Bs[lcol + 3][lrow] = wv.w;
        __syncthreads();
#pragma unroll
        for (int k = 0; k < 8; k++) {
            float a[8], b[8];
            *(float4*)(a)     = *(const float4*)&As[k][ty * 8];
            *(float4*)(a + 4) = *(const float4*)&As[k][ty * 8 + 4];
            *(float4*)(b)     = *(const float4*)&Bs[k][tx * 8];
            *(float4*)(b + 4) = *(const float4*)&Bs[k][tx * 8 + 4];
#pragma unroll
            for (int i = 0; i < 8; i++)
#pragma unroll
                for (int j = 0; j < 8; j++)
                    acc[i][j] = fmaf(a[i], b[j], acc[i][j]);
        }
        __syncthreads();
    }

    float* C = (which == 0) ? g_Q : (which == 1) ? g_K : g_V;
    const int padded = (which != 0);
#pragma unroll
    for (int i = 0; i < 8; i++) {
        int m  = m0 + ty * 8 + i;
        int om = padded ? (m + (m / SLEN) * (2 * WIN) + WIN) : m;
        float* cp = C + (size_t)om * DDIM + n0 + tx * 8;
        *(float4*)(cp)     = make_float4(acc[i][0], acc[i][1], acc[i][2], acc[i][3]);
        *(float4*)(cp + 4) = make_float4(acc[i][4], acc[i][5], acc[i][6], acc[i][7]);
    }
}

// ---------------------------------------------------------------------------
// Banded scores: for query tile (b, qbase) and key subtile nt (0..4),
// S[q, c] = (Q[q] . K[j]) / 32 with j = qbase - WIN + c, masked to the band.
// ---------------------------------------------------------------------------
__global__ void __launch_bounds__(256, 2) score_kernel()
{
    __shared__ __align__(16) float As[8][132];
    __shared__ __align__(16) float Bs[8][132];

    const int tid = threadIdx.x;
    const int tx  = tid & 15;
    const int ty  = tid >> 4;
    const int t   = blockIdx.y;                   // 0..127 global q-tile
    const int b   = t / QT_PER_B;
    const int qbase = (t % QT_PER_B) * 128;
    const int nt  = blockIdx.x;                   // 0..4
    const int jbase = qbase - WIN + nt * 128;
    const int lrow = tid >> 1;
    const int lcol = (tid & 1) * 4;

    const float* Ap = g_Q + (size_t)(b * SLEN + qbase + lrow) * DDIM + lcol;
    // padded key row for key j is (j + WIN); here row = qbase + nt*128 + lrow
    const float* Kp = g_K + (size_t)(b * SPAD + jbase + WIN + lrow) * DDIM + lcol;

    float acc[8][8];
#pragma unroll
    for (int i = 0; i < 8; i++)
#pragma unroll
        for (int j = 0; j < 8; j++) acc[i][j] = 0.f;

    for (int k0 = 0; k0 < DDIM; k0 += 8) {
        float4 av = *(const float4*)(Ap + k0);
        float4 kv = *(const float4*)(Kp + k0);
        As[lcol + 0][lrow] = av.x; As[lcol + 1][lrow] = av.y;
        As[lcol + 2][lrow] = av.z; As[lcol + 3][lrow] = av.w;
        Bs[lcol + 0][lrow] = kv.x; Bs[lcol + 1][lrow] = kv.y;
        Bs[lcol + 2][lrow] = kv.z; Bs[lcol + 3][lrow] = kv.w;
        __syncthreads();
#pragma unroll
        for (int k = 0; k < 8; k++) {
            float a[8], bb[8];
            *(float4*)(a)      = *(const float4*)&As[k][ty * 8];
            *(float4*)(a + 4)  = *(const float4*)&As[k][ty * 8 + 4];
            *(float4*)(bb)     = *(const float4*)&Bs[k][tx * 8];
            *(float4*)(bb + 4) = *(const float4*)&Bs[k][tx * 8 + 4];
#pragma unroll
            for (int i = 0; i < 8; i++)
#pragma unroll
                for (int j = 0; j < 8; j++)
                    acc[i][j] = fmaf(a[i], bb[j], acc[i][j]);
        }
        __syncthreads();
    }

    const float sc = 0.03125f;  // 1/sqrt(1024)
#pragma unroll
    for (int i = 0; i < 8; i++) {
        const int q = qbase + ty * 8 + i;
        float* pp = g_P + (size_t)(b * SLEN + q) * NCOL + nt * 128 + tx * 8;
#pragma unroll
        for (int j = 0; j < 8; j++) {
            const int jj = jbase + tx * 8 + j;
            const int d  = q - jj;
            const bool ok = (jj >= 0) && (jj < SLEN) && (d <= WIN) && (d >= -WIN);
            pp[j] = ok ? acc[i][j] * sc : NEGV;
        }
    }
}

// ---------------------------------------------------------------------------
// Row softmax over the 640 band columns (masked entries = -1e10 -> exp = 0).
// ---------------------------------------------------------------------------
__global__ void __launch_bounds__(128) softmax_kernel()
{
    const int r   = blockIdx.x;                 // 0..BATCH*SLEN-1
    float* row    = g_P + (size_t)r * NCOL;
    const int tid = threadIdx.x;

    float v[5];
    float mx = NEGV;
#pragma unroll
    for (int i = 0; i < 5; i++) {
        v[i] = row[tid + i * 128];
        mx = fmaxf(mx, v[i]);
    }
    __shared__ float red[4];
#pragma unroll
    for (int o = 16; o > 0; o >>= 1) mx = fmaxf(mx, __shfl_xor_sync(0xffffffffu, mx, o));
    if ((tid & 31) == 0) red[tid >> 5] = mx;
    __syncthreads();
    mx = fmaxf(fmaxf(red[0], red[1]), fmaxf(red[2], red[3]));

    float s = 0.f;
#pragma unroll
    for (int i = 0; i < 5; i++) {
        v[i] = __expf(v[i] - mx);
        s += v[i];
    }
#pragma unroll
    for (int o = 16; o > 0; o >>= 1) s += __shfl_xor_sync(0xffffffffu, s, o);
    __syncthreads();
    if ((tid & 31) == 0) red[tid >> 5] = s;
    __syncthreads();
    const float inv = 1.0f / (red[0] + red[1] + red[2] + red[3]);
#pragma unroll
    for (int i = 0; i < 5; i++) row[tid + i * 128] = v[i] * inv;
}

// ---------------------------------------------------------------------------
// Out[q, d] = sum_c P[q, c] * V[qbase - WIN + c, d]  (padded V row = qbase + c)
// ---------------------------------------------------------------------------
__global__ void __launch_bounds__(256, 2) av_kernel(float* __restrict__ out)
{
    __shared__ __align__(16) float As[8][132];
    __shared__ __align__(16) float Bs[8][132];

    const int tid = threadIdx.x;
    const int tx  = tid & 15;
    const int ty  = tid >> 4;
    const int t   = blockIdx.y;
    const int b   = t / QT_PER_B;
    const int qbase = (t % QT_PER_B) * 128;
    const int n0  = blockIdx.x * 128;
    const int lrow = tid >> 1;           // A loader
    const int lcol = (tid & 1) * 4;
    const int brow = tid >> 5;           // B loader (V rows, n-contiguous)
    const int bcol = (tid & 31) * 4;

    const float* Ap = g_P + (size_t)(b * SLEN + qbase + lrow) * NCOL + lcol;
    const float* Vp = g_V + (size_t)(b * SPAD + qbase + brow) * DDIM + n0 + bcol;

    float acc[8][8];
#pragma unroll
    for (int i = 0; i < 8; i++)
#pragma unroll
        for (int j = 0; j < 8; j++) acc[i][j] = 0.f;

    for (int k0 = 0; k0 < NCOL; k0 += 8) {
        float4 av = *(const float4*)(Ap + k0);
        float4 bv = *(const float4*)(Vp + (size_t)k0 * DDIM);
        As[lcol + 0][lrow] = av.x; As[lcol + 1][lrow] = av.y;
        As[lcol + 2][lrow] = av.z; As[lcol + 3][lrow] = av.w;
        *(float4*)&Bs[brow][bcol] = bv;
        __syncthreads();
#pragma unroll
        for (int k = 0; k < 8; k++) {
            float a[8], bb[8];
            *(float4*)(a)      = *(const float4*)&As[k][ty * 8];
            *(float4*)(a + 4)  = *(const float4*)&As[k][ty * 8 + 4];
            *(float4*)(bb)     = *(const float4*)&Bs[k][tx * 8];
            *(float4*)(bb + 4) = *(const float4*)&Bs[k][tx * 8 + 4];
#pragma unroll
            for (int i = 0; i < 8; i++)
#pragma unroll
                for (int j = 0; j < 8; j++)
                    acc[i][j] = fmaf(a[i], bb[j], acc[i][j]);
        }
        __syncthreads();
    }

#pragma unroll
    for (int i = 0; i < 8; i++) {
        const int q = qbase + ty * 8 + i;
        float* cp = out + (size_t)(b * SLEN + q) * DDIM + n0 + tx * 8;
        *(float4*)(cp)     = make_float4(acc[i][0], acc[i][1], acc[i][2], acc[i][3]);
        *(float4*)(cp + 4) = make_float4(acc[i][4], acc[i][5], acc[i][6], acc[i][7]);
    }
}

// ---------------------------------------------------------------------------
extern "C" void kernel_launch(void* const* d_in, const int* in_sizes, int n_in,
                              void* d_out, int out_size)
{
    (void)in_sizes; (void)n_in; (void)out_size;
    const float* X  = (const float*)d_in[0];
    const float* Y  = (const float*)d_in[1];
    const float* Wq = (const float*)d_in[2];
    const float* Wk = (const float*)d_in[3];
    const float* Wv = (const float*)d_in[4];
    float* out = (float*)d_out;

    dim3 gProj(DDIM / 128, (BATCH * SLEN) / 128);        // (8, 128)
    proj_kernel<<<gProj, 256>>>(Y, Wq, 0);               // Q = Y Wq^T
    proj_kernel<<<gProj, 256>>>(X, Wk, 1);               // K = X Wk^T (padded)
    proj_kernel<<<gProj, 256>>>(X, Wv, 2);               // V = X Wv^T (padded)

    score_kernel<<<dim3(5, BATCH * QT_PER_B), 256>>>();  // (5, 128)
    softmax_kernel<<<BATCH * SLEN, 128>>>();             // 16384 rows
    av_kernel<<<dim3(DDIM / 128, BATCH * QT_PER_B), 256>>>(out);
}

// round 3
// speedup vs baseline: 2.2100x; 2.2100x over previous
#include <cuda_runtime.h>
#include <cstdint>

#define BATCH 4
#define SLEN  4096
#define DDIM  1024
#define WIN   256
#define SPAD  (SLEN + 2 * WIN)        // 4608 padded seq rows (zeros in pads)
#define NCOL  (128 + 2 * WIN)         // 640 band columns per 128-query tile
#define QT_PER_B (SLEN / 128)
#define NEGV  (-1e10f)
#define RSTR  12                      // u32 row stride in smem (16 data + pad)

// Scratch device globals (zero-initialized at load; pads never written).
__device__ float g_Q [(size_t)BATCH * SLEN * DDIM];
__device__ float g_K [(size_t)BATCH * SPAD * DDIM];
__device__ float g_Vt[(size_t)BATCH * DDIM * SPAD];   // V transposed: [b][d][seq_pad]
__device__ float g_P [(size_t)BATCH * SLEN * NCOL];

// ---------------------------------------------------------------------------
// bf16x2 split helpers
// ---------------------------------------------------------------------------
__device__ __forceinline__ void cvt_split2(float f0, float f1, uint32_t& hi, uint32_t& lo)
{
    // packed reg: low 16 bits = f0 (even k), high 16 = f1 (odd k)
    asm("cvt.rn.bf16x2.f32 %0, %1, %2;" : "=r"(hi) : "f"(f1), "f"(f0));
    float h0 = __uint_as_float(hi << 16);
    float h1 = __uint_as_float(hi & 0xffff0000u);
    float l0 = f0 - h0;
    float l1 = f1 - h1;
    asm("cvt.rn.bf16x2.f32 %0, %1, %2;" : "=r"(lo) : "f"(l1), "f"(l0));
}

__device__ __forceinline__ void mma16816(float* d, const uint32_t* a, const uint32_t* b)
{
    asm volatile(
        "mma.sync.aligned.m16n8k16.row.col.f32.bf16.bf16.f32 "
        "{%0,%1,%2,%3}, {%4,%5,%6,%7}, {%8,%9}, {%0,%1,%2,%3};"
        : "+f"(d[0]), "+f"(d[1]), "+f"(d[2]), "+f"(d[3])
        : "r"(a[0]), "r"(a[1]), "r"(a[2]), "r"(a[3]), "r"(b[0]), "r"(b[1]));
}

// ---------------------------------------------------------------------------
// Unified GEMM: D[128,128] = A[128,K] * B[128,K]^T (both operands K-major)
// MODE 0: Q proj   1: K proj (padded rows)   2: V proj (transposed out)
// MODE 3: banded scores (mask epilogue)      4: attn*V (final output)
// ---------------------------------------------------------------------------
template<int MODE>
__global__ void __launch_bounds__(256, 1) gemm_kernel(const float* __restrict__ Ag,
                                                      const float* __restrict__ Bg,
                                                      float* __restrict__ Cg)
{
    // [stage][Ah, Al, Bh, Bl][128 rows * RSTR u32]  = 49152 bytes
    __shared__ uint32_t sm[2][4][128 * RSTR];

    const int tid = threadIdx.x;
    const int wid = tid >> 5;
    const int lid = tid & 31;
    const int g   = lid >> 2;          // group id 0..7
    const int tig = lid & 3;           // thread in group
    const int warpM = (wid & 3) * 32;  // 4 warps along M
    const int warpN = (wid >> 2) * 64; // 2 warps along N

    // ---- per-mode geometry ----
    const float* Abase; const float* Bbase;
    long strideA, strideB;
    int nc, b = 0, qbase = 0, nt = 0, m0 = 0, n0 = 0;
    if constexpr (MODE <= 2) {
        n0 = blockIdx.x * 128; m0 = blockIdx.y * 128;
        Abase = Ag + (size_t)m0 * DDIM; strideA = DDIM;
        Bbase = Bg + (size_t)n0 * DDIM; strideB = DDIM;
        nc = DDIM / 16;
    } else if constexpr (MODE == 3) {
        int t = blockIdx.y; b = t / QT_PER_B; qbase = (t % QT_PER_B) * 128;
        nt = blockIdx.x;
        Abase = g_Q + (size_t)(b * SLEN + qbase) * DDIM;             strideA = DDIM;
        Bbase = g_K + ((size_t)b * SPAD + qbase + nt * 128) * DDIM;  strideB = DDIM;
        nc = DDIM / 16;
    } else {
        int t = blockIdx.y; b = t / QT_PER_B; qbase = (t % QT_PER_B) * 128;
        n0 = blockIdx.x * 128;
        Abase = g_P  + (size_t)(b * SLEN + qbase) * NCOL;            strideA = NCOL;
        Bbase = g_Vt + ((size_t)b * DDIM + n0) * SPAD + qbase;       strideB = SPAD;
        nc = NCOL / 16;   // 40
    }

    // ---- producer lanes: thread -> (row, k-half) ----
    const int pr = tid >> 1;           // 0..127
    const int ph = tid & 1;            // 0/1 -> k offset 8*ph
    const float* Ar = Abase + (size_t)pr * strideA + ph * 8;
    const float* Br = Bbase + (size_t)pr * strideB + ph * 8;
    const int sidx = pr * RSTR + ph * 4;

    float acc[2][8][4];
#pragma unroll
    for (int mt = 0; mt < 2; mt++)
#pragma unroll
        for (int ntile = 0; ntile < 8; ntile++)
#pragma unroll
            for (int e = 0; e < 4; e++) acc[mt][ntile][e] = 0.f;

    // ---- helpers as lambdas ----
    auto cvt_store = [&](int st, float4 a0, float4 a1, float4 b0, float4 b1) {
        uint32_t h[4], l[4];
        cvt_split2(a0.x, a0.y, h[0], l[0]); cvt_split2(a0.z, a0.w, h[1], l[1]);
        cvt_split2(a1.x, a1.y, h[2], l[2]); cvt_split2(a1.z, a1.w, h[3], l[3]);
        *(uint4*)&sm[st][0][sidx] = make_uint4(h[0], h[1], h[2], h[3]);
        *(uint4*)&sm[st][1][sidx] = make_uint4(l[0], l[1], l[2], l[3]);
        cvt_split2(b0.x, b0.y, h[0], l[0]); cvt_split2(b0.z, b0.w, h[1], l[1]);
        cvt_split2(b1.x, b1.y, h[2], l[2]); cvt_split2(b1.z, b1.w, h[3], l[3]);
        *(uint4*)&sm[st][2][sidx] = make_uint4(h[0], h[1], h[2], h[3]);
        *(uint4*)&sm[st][3][sidx] = make_uint4(l[0], l[1], l[2], l[3]);
    };

    auto compute = [&](int st) {
        const uint32_t* sAh = sm[st][0];
        const uint32_t* sAl = sm[st][1];
        const uint32_t* sBh = sm[st][2];
        const uint32_t* sBl = sm[st][3];
        uint32_t ah[2][4], al[2][4];
#pragma unroll
        for (int mt = 0; mt < 2; mt++) {
            const int r0 = (warpM + mt * 16 + g) * RSTR;
            const int r8 = r0 + 8 * RSTR;
            ah[mt][0] = sAh[r0 + tig];     ah[mt][1] = sAh[r8 + tig];
            ah[mt][2] = sAh[r0 + tig + 4]; ah[mt][3] = sAh[r8 + tig + 4];
            al[mt][0] = sAl[r0 + tig];     al[mt][1] = sAl[r8 + tig];
            al[mt][2] = sAl[r0 + tig + 4]; al[mt][3] = sAl[r8 + tig + 4];
        }
#pragma unroll
        for (int ntile = 0; ntile < 8; ntile++) {
            const int c0 = (warpN + ntile * 8 + g) * RSTR;
            uint32_t bh[2], bl[2];
            bh[0] = sBh[c0 + tig]; bh[1] = sBh[c0 + tig + 4];
            bl[0] = sBl[c0 + tig]; bl[1] = sBl[c0 + tig + 4];
#pragma unroll
            for (int mt = 0; mt < 2; mt++) {
                mma16816(acc[mt][ntile], ah[mt], bh);
                mma16816(acc[mt][ntile], ah[mt], bl);
                mma16816(acc[mt][ntile], al[mt], bh);
            }
        }
    };

    // ---- prologue: chunk 0 ----
    {
        float4 a0 = *(const float4*)(Ar);
        float4 a1 = *(const float4*)(Ar + 4);
        float4 b0 = *(const float4*)(Br);
        float4 b1 = *(const float4*)(Br + 4);
        cvt_store(0, a0, a1, b0, b1);
    }
    __syncthreads();

    // ---- main loop ----
    for (int c = 0; c < nc; c++) {
        float4 na0, na1, nb0, nb1;
        const bool more = (c + 1 < nc);
        if (more) {
            const float* ap = Ar + (size_t)(c + 1) * 16;
            const float* bp = Br + (size_t)(c + 1) * 16;
            na0 = *(const float4*)(ap);
            na1 = *(const float4*)(ap + 4);
            nb0 = *(const float4*)(bp);
            nb1 = *(const float4*)(bp + 4);
        }
        compute(c & 1);
        if (more) cvt_store((c + 1) & 1, na0, na1, nb0, nb1);
        __syncthreads();
    }

    // ---- epilogue ----
#pragma unroll
    for (int mt = 0; mt < 2; mt++) {
#pragma unroll
        for (int ntile = 0; ntile < 8; ntile++) {
            const float* a = acc[mt][ntile];
            const int rlo = warpM + mt * 16 + g;
            const int rhi = rlo + 8;
            const int cn  = warpN + ntile * 8 + 2 * tig;
            if constexpr (MODE == 0) {
                float* p0 = g_Q + (size_t)(m0 + rlo) * DDIM + n0 + cn;
                float* p1 = g_Q + (size_t)(m0 + rhi) * DDIM + n0 + cn;
                p0[0] = a[0]; p0[1] = a[1]; p1[0] = a[2]; p1[1] = a[3];
            } else if constexpr (MODE == 1) {
                const int mA = m0 + rlo, mB = m0 + rhi;
                float* p0 = g_K + ((size_t)(mA >> 12) * SPAD + (mA & (SLEN - 1)) + WIN) * DDIM + n0 + cn;
                float* p1 = g_K + ((size_t)(mB >> 12) * SPAD + (mB & (SLEN - 1)) + WIN) * DDIM + n0 + cn;
                p0[0] = a[0]; p0[1] = a[1]; p1[0] = a[2]; p1[1] = a[3];
            } else if constexpr (MODE == 2) {
                const int mA = m0 + rlo, mB = m0 + rhi;
                const size_t sA = (size_t)(mA >> 12) * DDIM, qA = (mA & (SLEN - 1)) + WIN;
                const size_t sB = (size_t)(mB >> 12) * DDIM, qB = (mB & (SLEN - 1)) + WIN;
                g_Vt[(sA + n0 + cn)     * SPAD + qA] = a[0];
                g_Vt[(sA + n0 + cn + 1) * SPAD + qA] = a[1];
                g_Vt[(sB + n0 + cn)     * SPAD + qB] = a[2];
                g_Vt[(sB + n0 + cn + 1) * SPAD + qB] = a[3];
            } else if constexpr (MODE == 3) {
                const int jbase = qbase - WIN + nt * 128 + cn;
                float* p0 = g_P + (size_t)(b * SLEN + qbase + rlo) * NCOL + nt * 128 + cn;
                float* p1 = g_P + (size_t)(b * SLEN + qbase + rhi) * NCOL + nt * 128 + cn;
#pragma unroll
                for (int e = 0; e < 2; e++) {
                    const int jj = jbase + e;
                    {
                        const int q = qbase + rlo, d = q - jj;
                        p0[e] = (jj >= 0 && jj < SLEN && d <= WIN && d >= -WIN)
                                ? a[e] * 0.03125f : NEGV;
                    }
                    {
                        const int q = qbase + rhi, d = q - jj;
                        p1[e] = (jj >= 0 && jj < SLEN && d <= WIN && d >= -WIN)
                                ? a[e + 2] * 0.03125f : NEGV;
                    }
                }
            } else {
                float* p0 = Cg + ((size_t)b * SLEN + qbase + rlo) * DDIM + n0 + cn;
                float* p1 = Cg + ((size_t)b * SLEN + qbase + rhi) * DDIM + n0 + cn;
                p0[0] = a[0]; p0[1] = a[1]; p1[0] = a[2]; p1[1] = a[3];
            }
        }
    }
}

// ---------------------------------------------------------------------------
// Row softmax over 640 band columns (masked entries -1e10 -> exp 0)
// ---------------------------------------------------------------------------
__global__ void __launch_bounds__(128) softmax_kernel()
{
    const int r = blockIdx.x;
    float* row = g_P + (size_t)r * NCOL;
    const int tid = threadIdx.x;

    float v[5];
    float mx = NEGV;
#pragma unroll
    for (int i = 0; i < 5; i++) { v[i] = row[tid + i * 128]; mx = fmaxf(mx, v[i]); }
    __shared__ float red[4];
#pragma unroll
    for (int o = 16; o > 0; o >>= 1) mx = fmaxf(mx, __shfl_xor_sync(0xffffffffu, mx, o));
    if ((tid & 31) == 0) red[tid >> 5] = mx;
    __syncthreads();
    mx = fmaxf(fmaxf(red[0], red[1]), fmaxf(red[2], red[3]));

    float s = 0.f;
#pragma unroll
    for (int i = 0; i < 5; i++) { v[i] = __expf(v[i] - mx); s += v[i]; }
#pragma unroll
    for (int o = 16; o > 0; o >>= 1) s += __shfl_xor_sync(0xffffffffu, s, o);
    __syncthreads();
    if ((tid & 31) == 0) red[tid >> 5] = s;
    __syncthreads();
    const float inv = 1.0f / (red[0] + red[1] + red[2] + red[3]);
#pragma unroll
    for (int i = 0; i < 5; i++) row[tid + i * 128] = v[i] * inv;
}

// ---------------------------------------------------------------------------
extern "C" void kernel_launch(void* const* d_in, const int* in_sizes, int n_in,
                              void* d_out, int out_size)
{
    (void)in_sizes; (void)n_in; (void)out_size;
    const float* X  = (const float*)d_in[0];
    const float* Y  = (const float*)d_in[1];
    const float* Wq = (const float*)d_in[2];
    const float* Wk = (const float*)d_in[3];
    const float* Wv = (const float*)d_in[4];
    float* out = (float*)d_out;

    const dim3 gProj(DDIM / 128, (BATCH * SLEN) / 128);   // (8, 128)
    gemm_kernel<0><<<gProj, 256>>>(Y, Wq, nullptr);       // Q = Y Wq^T
    gemm_kernel<1><<<gProj, 256>>>(X, Wk, nullptr);       // K (padded rows)
    gemm_kernel<2><<<gProj, 256>>>(X, Wv, nullptr);       // V (transposed)
    gemm_kernel<3><<<dim3(5, BATCH * QT_PER_B), 256>>>(nullptr, nullptr, nullptr);
    softmax_kernel<<<BATCH * SLEN, 128>>>();
    gemm_kernel<4><<<dim3(DDIM / 128, BATCH * QT_PER_B), 256>>>(nullptr, nullptr, out);
}